// round 6
// baseline (speedup 1.0000x reference)
#include <cuda_runtime.h>

#define NBINS   256
#define TPB     256                         // 8 warps
#define KQ      7                           // quads cached in registers per thread
#define NBLOCKS 148
#define HIST_BYTES (2 * NBINS * 256)        // 128 KB: 256B per (table,bin), byte per thread
#define CHUNK_Q (NBLOCKS * TPB * 48)        // spill-path chunk: <=192 incs per u8

__device__ int   g_hist[2 * NBINS];      // zero-init; restored to zero each run
__device__ float g_pxmap[NBINS];
__device__ int   g_done0;
__device__ int   g_done1;
__device__ volatile int g_release;

extern __shared__ unsigned char s_dyn[]; // dynamic: u8 histogram counters

__device__ __forceinline__ int bin_of(float x) {
    return min(max((int)(x * 256.0f), 0), NBINS - 1);
}

// Merge duplicate bins within a 4-tuple; counts land on the first occurrence.
__device__ __forceinline__ void merge4(int b0, int b1, int b2, int b3,
                                       int& c0, int& c1, int& c2, int& c3) {
    c0 = 1; c1 = 1; c2 = 1; c3 = 1;
    if (b1 == b0) { c0 += c1; c1 = 0; }
    if (b2 == b0) { c0 += c2; c2 = 0; }
    else if (b2 == b1) { c1 += c2; c2 = 0; }
    if (b3 == b0) { c0 += c3; c3 = 0; }
    else if (b3 == b1) { c1 += c3; c3 = 0; }
    else if (b3 == b2) { c2 += c3; c3 = 0; }
}

// 8 counter RMWs with all loads batched before all stores (overlapped LDS).
// Active addresses are distinct after merge4 -> predicated stores are safe.
__device__ __forceinline__ void count8(unsigned char* hp, int myoff,
                                       int b0, int b1, int b2, int b3,
                                       int d0, int d1, int d2, int d3) {
    int c0, c1, c2, c3, e0, e1, e2, e3;
    merge4(b0, b1, b2, b3, c0, c1, c2, c3);
    merge4(d0, d1, d2, d3, e0, e1, e2, e3);
    unsigned char* p0 = hp + (b0 << 8) + myoff;
    unsigned char* p1 = hp + (b1 << 8) + myoff;
    unsigned char* p2 = hp + (b2 << 8) + myoff;
    unsigned char* p3 = hp + (b3 << 8) + myoff;
    unsigned char* q0 = hp + ((NBINS + d0) << 8) + myoff;
    unsigned char* q1 = hp + ((NBINS + d1) << 8) + myoff;
    unsigned char* q2 = hp + ((NBINS + d2) << 8) + myoff;
    unsigned char* q3 = hp + ((NBINS + d3) << 8) + myoff;
    unsigned int v0 = *p0, v1 = *p1, v2 = *p2, v3 = *p3;
    unsigned int u0 = *q0, u1 = *q1, u2 = *q2, u3 = *q3;
    *p0 = (unsigned char)(v0 + c0);                      // c0 >= 1 always
    if (c1) *p1 = (unsigned char)(v1 + c1);
    if (c2) *p2 = (unsigned char)(v2 + c2);
    if (c3) *p3 = (unsigned char)(v3 + c3);
    *q0 = (unsigned char)(u0 + e0);
    if (e1) *q1 = (unsigned char)(u1 + e1);
    if (e2) *q2 = (unsigned char)(u2 + e2);
    if (e3) *q3 = (unsigned char)(u3 + e3);
}

// Branchless per-pixel interpolate on the fixed fs grid + clip + rescale-back.
__device__ __forceinline__ float apply1(float x,
                                        const float* __restrict__ fsv,
                                        const float* __restrict__ As,
                                        const float* __restrict__ Bs,
                                        float pm0, float pm255,
                                        float fs0, float fs255) {
    int j = (int)(x * 255.0f) + 1;
    j = min(max(j, 1), NBINS - 1);
    if (fsv[j - 1] > x) --j;
    j = max(j, 1);
    if (fsv[j] <= x) ++j;
    j = min(j, NBINS - 1);
    float r = fmaf(As[j], x, Bs[j]);
    if (x <= fs0)   r = pm0;
    if (x >= fs255) r = pm255;
    r = fminf(fmaxf(r, 0.0f), 1.0f);
    return fmaf(r, 255.0f / 127.0f, -1.0f);
}

__global__ void __launch_bounds__(TPB, 1) k_fused(const float* __restrict__ src,
                                                  const float* __restrict__ tgt,
                                                  float* __restrict__ out, int n) {
    __shared__ int   sh[2 * NBINS];
    __shared__ float fsv[NBINS], pmS[NBINS], As[NBINS], Bs[NBINS];
    __shared__ int   is_last;

    const int t     = threadIdx.x;
    const int lane  = t & 31;
    const int wid   = t >> 5;
    // byte offset within a bin's 256B region: 4 warps per 128B row, lane-word,
    // warp-byte -> 256 distinct offsets, conflict-free within each warp.
    const int myoff = (wid >> 2) * 128 + (lane << 2) + (wid & 3);
    const int nth   = gridDim.x * TPB;
    const int gtid  = blockIdx.x * TPB + t;
    const int nq    = n >> 2;
    const float SC  = 127.0f / 255.0f;

    unsigned char* hp = s_dyn;

    if (t < NBINS) {   // floating_space: np.arange semantics (f64 i*step -> f32)
        float v = (float)((double)t * (1.0 / 255.0));
        fsv[t] = fminf(fmaxf(v, 0.0f), 1.0f);
    }

    const float4* s4 = (const float4*)src;
    const float4* t4 = (const float4*)tgt;
    float4*       o4 = (float4*)out;

    const bool cached = (nq <= KQ * nth) && (nq <= CHUNK_Q);

    // ================= Phase 1: counting =================
    float xr[4 * KQ];

    if (cached) {
        // zero counters
        {
            uint4* z = (uint4*)s_dyn;
            #pragma unroll
            for (int i = 0; i < HIST_BYTES / 16 / TPB; ++i)
                z[t + i * TPB] = make_uint4(0, 0, 0, 0);
        }
        __syncthreads();

        #pragma unroll
        for (int k = 0; k < KQ; ++k) {
            int q = gtid + k * nth;
            if (q < nq) {
                float4 a = s4[3 * q + 0];
                float4 b = s4[3 * q + 1];
                float4 c = s4[3 * q + 2];
                float4 ta = t4[3 * q + 0];
                float4 tb = t4[3 * q + 1];
                float4 tc = t4[3 * q + 2];
                float x0 = (a.x + 1.0f) * SC, x1 = (a.w + 1.0f) * SC;
                float x2 = (b.z + 1.0f) * SC, x3 = (c.y + 1.0f) * SC;
                xr[4 * k + 0] = x0; xr[4 * k + 1] = x1;
                xr[4 * k + 2] = x2; xr[4 * k + 3] = x3;
                float y0 = (ta.x + 1.0f) * SC * 0.299f + (ta.y + 1.0f) * SC * 0.587f + (ta.z + 1.0f) * SC * 0.114f;
                float y1 = (ta.w + 1.0f) * SC * 0.299f + (tb.x + 1.0f) * SC * 0.587f + (tb.y + 1.0f) * SC * 0.114f;
                float y2 = (tb.z + 1.0f) * SC * 0.299f + (tb.w + 1.0f) * SC * 0.587f + (tc.x + 1.0f) * SC * 0.114f;
                float y3 = (tc.y + 1.0f) * SC * 0.299f + (tc.z + 1.0f) * SC * 0.587f + (tc.w + 1.0f) * SC * 0.114f;
                count8(hp, myoff,
                       bin_of(x0), bin_of(x1), bin_of(x2), bin_of(x3),
                       bin_of(y0), bin_of(y1), bin_of(y2), bin_of(y3));
            }
        }
        __syncthreads();

        // reduction: one warp per (table,bin); coalesced, conflict-free
        {
            const unsigned int* w32 = (const unsigned int*)hp;
            for (int r = wid; r < 2 * NBINS; r += TPB / 32) {
                const unsigned int* row = w32 + (r << 6);   // 64 words per bin
                unsigned int s = __dp4a(row[lane], 0x01010101u,
                                 __dp4a(row[lane + 32], 0x01010101u, 0u));
                s = __reduce_add_sync(0xffffffffu, s);
                if (lane == 0 && s) atomicAdd(&g_hist[r], (int)s);
            }
        }
    } else {
        // general-n spill path: chunked, x spilled to out
        for (int cbase = 0; cbase < nq; cbase += CHUNK_Q) {
            const int cend = min(cbase + CHUNK_Q, nq);
            {
                uint4* z = (uint4*)s_dyn;
                #pragma unroll
                for (int i = 0; i < HIST_BYTES / 16 / TPB; ++i)
                    z[t + i * TPB] = make_uint4(0, 0, 0, 0);
            }
            __syncthreads();
            for (int q = cbase + gtid; q < cend; q += nth) {
                float4 a = s4[3 * q + 0];
                float4 b = s4[3 * q + 1];
                float4 c = s4[3 * q + 2];
                float4 ta = t4[3 * q + 0];
                float4 tb = t4[3 * q + 1];
                float4 tc = t4[3 * q + 2];
                float x0 = (a.x + 1.0f) * SC, x1 = (a.w + 1.0f) * SC;
                float x2 = (b.z + 1.0f) * SC, x3 = (c.y + 1.0f) * SC;
                o4[q] = make_float4(x0, x1, x2, x3);
                float y0 = (ta.x + 1.0f) * SC * 0.299f + (ta.y + 1.0f) * SC * 0.587f + (ta.z + 1.0f) * SC * 0.114f;
                float y1 = (ta.w + 1.0f) * SC * 0.299f + (tb.x + 1.0f) * SC * 0.587f + (tb.y + 1.0f) * SC * 0.114f;
                float y2 = (tb.z + 1.0f) * SC * 0.299f + (tb.w + 1.0f) * SC * 0.587f + (tc.x + 1.0f) * SC * 0.114f;
                float y3 = (tc.y + 1.0f) * SC * 0.299f + (tc.z + 1.0f) * SC * 0.587f + (tc.w + 1.0f) * SC * 0.114f;
                count8(hp, myoff,
                       bin_of(x0), bin_of(x1), bin_of(x2), bin_of(x3),
                       bin_of(y0), bin_of(y1), bin_of(y2), bin_of(y3));
            }
            __syncthreads();
            {
                const unsigned int* w32 = (const unsigned int*)hp;
                for (int r = wid; r < 2 * NBINS; r += TPB / 32) {
                    const unsigned int* row = w32 + (r << 6);
                    unsigned int s = __dp4a(row[lane], 0x01010101u,
                                     __dp4a(row[lane + 32], 0x01010101u, 0u));
                    s = __reduce_add_sync(0xffffffffu, s);
                    if (lane == 0 && s) atomicAdd(&g_hist[r], (int)s);
                }
            }
            __syncthreads();
        }
    }

    // Tail pixels (n % 4): at most 3, via global atomics, x spilled to out.
    const int tidx = 4 * nq + gtid;
    if (tidx < n) {
        float x = (src[3 * tidx] + 1.0f) * SC;
        out[tidx] = x;
        atomicAdd(&g_hist[bin_of(x)], 1);
        float yr = (tgt[3 * tidx + 0] + 1.0f) * SC;
        float yg = (tgt[3 * tidx + 1] + 1.0f) * SC;
        float yb = (tgt[3 * tidx + 2] + 1.0f) * SC;
        atomicAdd(&g_hist[NBINS + bin_of(yr * 0.299f + yg * 0.587f + yb * 0.114f)], 1);
    }

    // ================= Device-wide barrier =================
    __syncthreads();
    if (t == 0) {
        __threadfence();
        int old = atomicAdd(&g_done0, 1);
        is_last = (old == (int)gridDim.x - 1);
    }
    __syncthreads();

    if (is_last) {
        __threadfence();
        sh[t]         = *(volatile int*)&g_hist[t];
        sh[t + NBINS] = *(volatile int*)&g_hist[t + NBINS];
        __syncthreads();
        #pragma unroll
        for (int off = 1; off < NBINS; off <<= 1) {
            int aself = sh[t], bself = sh[t + NBINS];
            int aprev = (t >= off) ? sh[t - off] : 0;
            int bprev = (t >= off) ? sh[t + NBINS - off] : 0;
            __syncthreads();
            sh[t] = aself + aprev;
            sh[t + NBINS] = bself + bprev;
            __syncthreads();
        }
        {
            int mint = sh[NBINS];
            As[t] = (float)(sh[t + NBINS] - mint) / (float)(n - 1);  // cdftgt
        }
        __syncthreads();
        {
            int mins = sh[0];
            float x = (float)(sh[t] - mins) / (float)(n - 1);        // cdfsrc
            int lo = 0, hi = NBINS - 1;
            while (lo < hi) { int mid = (lo + hi) >> 1; if (As[mid] > x) hi = mid; else lo = mid + 1; }
            int ind1 = lo;
            int ind0 = max(ind1 - 1, 0);
            float dx0 = As[ind0], dx1 = As[ind1];
            float dy0 = fsv[ind0], dy1 = fsv[ind1];
            float dnm = dx1 - dx0;
            float sd  = (dnm == 0.0f) ? 1.0f : dnm;
            float interp = dy0 + (dy1 - dy0) * (x - dx0) / sd;
            float res = (x <= As[0]) ? fsv[0]
                      : ((x >= As[NBINS - 1]) ? fsv[NBINS - 1] : interp);
            pmS[t] = res;
            g_pxmap[t] = res;
        }
        __threadfence();
        __syncthreads();
        if (t == 0) g_release = 1;
    } else {
        if (t == 0) {
            while (g_release == 0) __nanosleep(32);
            __threadfence();   // acquire
        }
        __syncthreads();
        pmS[t] = __ldcg(&g_pxmap[t]);
    }
    __syncthreads();

    // ---- slope/intercept tables ----
    if (t > 0) {
        float d = fsv[t] - fsv[t - 1];          // strictly > 0
        float a = (pmS[t] - pmS[t - 1]) / d;
        As[t] = a;
        Bs[t] = pmS[t - 1] - a * fsv[t - 1];
    }
    __syncthreads();

    // ================= Phase 3: apply =================
    const float pm0 = pmS[0], pm255 = pmS[NBINS - 1];
    const float fs0 = fsv[0], fs255 = fsv[NBINS - 1];

    if (cached) {
        #pragma unroll
        for (int k = 0; k < KQ; ++k) {
            int q = gtid + k * nth;
            if (q < nq) {
                float4 v;
                v.x = apply1(xr[4 * k + 0], fsv, As, Bs, pm0, pm255, fs0, fs255);
                v.y = apply1(xr[4 * k + 1], fsv, As, Bs, pm0, pm255, fs0, fs255);
                v.z = apply1(xr[4 * k + 2], fsv, As, Bs, pm0, pm255, fs0, fs255);
                v.w = apply1(xr[4 * k + 3], fsv, As, Bs, pm0, pm255, fs0, fs255);
                o4[q] = v;
            }
        }
    } else {
        for (int q = gtid; q < nq; q += nth) {
            float4 v = o4[q];
            v.x = apply1(v.x, fsv, As, Bs, pm0, pm255, fs0, fs255);
            v.y = apply1(v.y, fsv, As, Bs, pm0, pm255, fs0, fs255);
            v.z = apply1(v.z, fsv, As, Bs, pm0, pm255, fs0, fs255);
            v.w = apply1(v.w, fsv, As, Bs, pm0, pm255, fs0, fs255);
            o4[q] = v;
        }
    }
    if (tidx < n) out[tidx] = apply1(out[tidx], fsv, As, Bs, pm0, pm255, fs0, fs255);

    // ================= Cleanup for next replay =================
    __syncthreads();
    if (t == 0) {
        __threadfence();
        int old = atomicAdd(&g_done1, 1);
        if (old == (int)gridDim.x - 1) {
            #pragma unroll 8
            for (int i = 0; i < 2 * NBINS; ++i) g_hist[i] = 0;
            g_done0 = 0;
            g_done1 = 0;
            __threadfence();
            g_release = 0;
        }
    }
}

extern "C" void kernel_launch(void* const* d_in, const int* in_sizes, int n_in,
                              void* d_out, int out_size) {
    const float* src = (const float*)d_in[0];
    const float* tgt = (const float*)d_in[1];
    float* out = (float*)d_out;
    int n = in_sizes[0] / 3;   // H*W pixels

    cudaFuncSetAttribute(k_fused, cudaFuncAttributeMaxDynamicSharedMemorySize,
                         HIST_BYTES);

    k_fused<<<NBLOCKS, TPB, HIST_BYTES>>>(src, tgt, out, n);
}